// round 11
// baseline (speedup 1.0000x reference)
#include <cuda_runtime.h>
#include <cstdint>

#define N_TOK 12288
#define DHEAD 128
#define NUMB  32
#define BM 64
#define BN 64
#define KSPLIT 128
#define MAXPARTS 6
#define NTHREADS 256
#define NWORKERS 296

__device__ int  g_seg_start[NUMB + 1];
__device__ float g_pO[MAXPARTS][N_TOK][DHEAD];  // unnormalized partial O
__device__ float g_pl[MAXPARTS][N_TOK];          // partial row sums

// ---------------------------------------------------------------------------
// PTX helpers
// ---------------------------------------------------------------------------
__device__ __forceinline__ void mbar_init(uint32_t mbar) {
    asm volatile("mbarrier.init.shared.b64 [%0], 1;" :: "r"(mbar) : "memory");
}
__device__ __forceinline__ void mbar_expect(uint32_t mbar, uint32_t bytes) {
    asm volatile("mbarrier.arrive.expect_tx.shared.b64 _, [%0], %1;"
                 :: "r"(mbar), "r"(bytes) : "memory");
}
__device__ __forceinline__ void mbar_wait(uint32_t mbar, uint32_t phase) {
    asm volatile(
        "{\n\t.reg .pred P;\n\t"
        "WAIT_%=:\n\t"
        "mbarrier.try_wait.parity.acquire.cta.shared::cta.b64 P, [%0], %1, 0x989680;\n\t"
        "@P bra.uni DONE_%=;\n\t"
        "bra.uni WAIT_%=;\n\t"
        "DONE_%=:\n\t}"
        :: "r"(mbar), "r"(phase) : "memory");
}
__device__ __forceinline__ void fence_async() {
    asm volatile("fence.proxy.async.shared::cta;" ::: "memory");
}
__device__ __forceinline__ void bulk_g2s(uint32_t dst, const void* src,
                                         uint32_t bytes, uint32_t mbar) {
    asm volatile(
        "cp.async.bulk.shared::cluster.global.mbarrier::complete_tx::bytes "
        "[%0], [%1], %2, [%3];"
        :: "r"(dst), "l"(src), "r"(bytes), "r"(mbar) : "memory");
}
__device__ __forceinline__ void fma2(unsigned long long& d,
                                     const unsigned long long a,
                                     const unsigned long long b) {
    asm volatile("fma.rn.f32x2 %0, %1, %2, %0;" : "+l"(d) : "l"(a), "l"(b));
}
__device__ __forceinline__ unsigned long long dup2(float x) {
    unsigned long long d;
    asm("mov.b64 %0, {%1, %1};" : "=l"(d) : "f"(x));
    return d;
}

// ---------------------------------------------------------------------------
// Main kernel. Self-contained: derives segment table per-CTA (no prep kernel),
// static item schedule (w = blockIdx.x + k*gridDim.x), cross-item Q+K prefetch
// during the last tile's PV. 256 threads = 8 warps; warp wy owns rows
// wy*8..+7; lane tx owns score cols {2tx,2tx+1}, output cols 4tx..+3.
// Linear smem; bulk copies; QK conflict-free via chunk rotation c^(tx&7)
// applied to BOTH Q and K (bijection, exact).
// ---------------------------------------------------------------------------
__global__ __launch_bounds__(NTHREADS, 2)
void attn_kernel(const float* __restrict__ Q, const float* __restrict__ K,
                 const float* __restrict__ V, const int* __restrict__ bseg) {
    extern __shared__ float smf[];
    float* Qs = smf;            // [64][128] 32KB linear
    float* Ab = smf + 8192;     // [64][128] 32KB linear (K tile)
    float* Bb = smf + 16384;    // [64][128] 32KB linear (V tile)
    float* Ps = smf + 24576;    // [64][64]  16KB (e0,e1) pairs
    __shared__ int s_seg[NUMB + 1];
    __shared__ int s_iofs[NUMB + 1];
    __shared__ unsigned long long s_mbar[2];

    const int tid = threadIdx.x;
    const int tx  = tid & 31;
    const int wy  = tid >> 5;                 // 0..7
    const uint32_t sm_u = (uint32_t)__cvta_generic_to_shared(smf);
    const uint32_t qs_u = sm_u;
    const uint32_t a_u  = sm_u + 8192u * 4u;
    const uint32_t b_u  = sm_u + 16384u * 4u;
    const uint32_t mbA  = (uint32_t)__cvta_generic_to_shared(&s_mbar[0]);
    const uint32_t mbB  = (uint32_t)__cvta_generic_to_shared(&s_mbar[1]);
    const float isd = 0.0883883476483184f;    // 1/sqrt(128)
    const int e = tx & 7;                     // chunk rotation

    // ---- in-kernel init: segment boundaries (strided detect) ----
    for (int i = tid; i < N_TOK; i += NTHREADS) {
        if (i == 0) {
            int c = bseg[0];
            for (int b2 = 0; b2 <= c; b2++) s_seg[b2] = 0;
        } else {
            int a = bseg[i - 1], c = bseg[i];
            for (int b2 = a + 1; b2 <= c; b2++) s_seg[b2] = i;
        }
    }
    if (tid == 0) {
        int last = bseg[N_TOK - 1];
        for (int b2 = last + 1; b2 <= NUMB; b2++) s_seg[b2] = N_TOK;
        mbar_init(mbA); mbar_init(mbB); fence_async();
    }
    // zero-init Q/A/B once (prevents NaN poison from uninit smem)
    #pragma unroll
    for (int t = 0; t < 24; t++)
        *(float4*)(smf + (tid + t * NTHREADS) * 4) =
            make_float4(0.f, 0.f, 0.f, 0.f);
    __syncthreads();
    if (tid == 0) {
        int run = 0;
        for (int b2 = 0; b2 < NUMB; b2++) {
            s_iofs[b2] = run;
            int rows = s_seg[b2 + 1] - s_seg[b2];
            run += ((rows + BM - 1) / BM) * ((rows + KSPLIT - 1) / KSPLIT);
        }
        s_iofs[NUMB] = run;
    }
    if (blockIdx.x == 0 && tid <= NUMB) g_seg_start[tid] = s_seg[tid];
    __syncthreads();
    const int nitems = s_iofs[NUMB];

    uint32_t phA = 0, phB = 0;
    bool prefetched = false;

    for (int w = blockIdx.x; w < nitems; w += gridDim.x) {
        // ---- map item w -> (r0, nrows, klo, khi, part) ----
        int b2 = 0;
        while (w >= s_iofs[b2 + 1]) b2++;
        int rel = w - s_iofs[b2];
        int lo = s_seg[b2], hi = s_seg[b2 + 1];
        int nkp = (hi - lo + KSPLIT - 1) / KSPLIT;
        int rt  = rel / nkp;
        int part = rel - rt * nkp;
        const int r0    = lo + rt * BM;
        const int nrows = min(BM, hi - r0);
        const int klo   = lo + part * KSPLIT;
        const int khi   = min(klo + KSPLIT, hi);

        // ---- map next item (for prefetch during last tile) ----
        const int wn = w + gridDim.x;
        const bool hasnext_item = (wn < nitems);
        int r0n = 0, klon = 0;
        if (hasnext_item) {
            int b3 = b2;
            while (wn >= s_iofs[b3 + 1]) b3++;
            int rel2 = wn - s_iofs[b3];
            int lo2 = s_seg[b3], hi2 = s_seg[b3 + 1];
            int nkp2 = (hi2 - lo2 + KSPLIT - 1) / KSPLIT;
            int rt2 = rel2 / nkp2;
            r0n  = lo2 + rt2 * BM;
            klon = lo2 + (rel2 - rt2 * nkp2) * KSPLIT;
        }

        // ---- first item: issue Q + K(0) here (later items: prefetched) ----
        if (!prefetched && tid == 0) {
            uint32_t qb = (uint32_t)min(BM, N_TOK - r0) * 512u;
            uint32_t kb = (uint32_t)min(BM, N_TOK - klo) * 512u;
            fence_async();
            mbar_expect(mbA, qb + kb);
            bulk_g2s(qs_u, Q + (size_t)r0 * DHEAD, qb, mbA);
            bulk_g2s(a_u,  K + (size_t)klo * DHEAD, kb, mbA);
        }

        unsigned long long o2[8][2];
        float lsum[8];
        #pragma unroll
        for (int i = 0; i < 8; i++) { o2[i][0] = 0ULL; o2[i][1] = 0ULL; lsum[i] = 0.f; }

        for (int kt = klo; kt < khi; kt += BN) {
            mbar_wait(mbA, phA); phA ^= 1;    // Q+K(0) or K(t) ready

            // Issue V(t) -> B (B free: PV-end sync of previous tile)
            if (tid == 0) {
                uint32_t vb = (uint32_t)min(BM, N_TOK - kt) * 512u;
                fence_async();
                mbar_expect(mbB, vb);
                bulk_g2s(b_u, V + (size_t)kt * DHEAD, vb, mbB);
            }

            // ---- QK: 8 rows x 2 cols per lane, rotated chunks ----
            const float* kp0 = Ab + (2 * tx) * 128;
            const float* qp  = Qs + (wy * 8) * 128;
            unsigned long long s2[8][2];
            #pragma unroll
            for (int i = 0; i < 8; i++) { s2[i][0] = 0ULL; s2[i][1] = 0ULL; }

            #pragma unroll 4
            for (int c = 0; c < 32; c++) {
                int kph = (c ^ e) << 2;
                ulonglong2 ka = *(const ulonglong2*)(kp0 + kph);
                ulonglong2 kb = *(const ulonglong2*)(kp0 + 128 + kph);
                const float* qc = qp + kph;
                #pragma unroll
                for (int i = 0; i < 8; i++) {
                    ulonglong2 qa = *(const ulonglong2*)(qc + i * 128);
                    fma2(s2[i][0], qa.x, ka.x);
                    fma2(s2[i][0], qa.y, ka.y);
                    fma2(s2[i][1], qa.x, kb.x);
                    fma2(s2[i][1], qa.y, kb.y);
                }
            }

            // ---- masked exp, P store (e0,e1) once (warp-private rows) ----
            const int col0 = kt + 2 * tx;
            #pragma unroll
            for (int i = 0; i < 8; i++) {
                unsigned long long v0 = s2[i][0], v1 = s2[i][1];
                float sv0 = (__uint_as_float((unsigned)v0) +
                             __uint_as_float((unsigned)(v0 >> 32))) * isd;
                float sv1 = (__uint_as_float((unsigned)v1) +
                             __uint_as_float((unsigned)(v1 >> 32))) * isd;
                float e0 = (col0     < khi) ? __expf(sv0) : 0.f;
                float e1 = (col0 + 1 < khi) ? __expf(sv1) : 0.f;
                lsum[i] += e0 + e1;
                float2 ev; ev.x = e0; ev.y = e1;
                *(float2*)(Ps + (wy * 8 + i) * 64 + tx * 2) = ev;
            }
            __syncthreads();                  // all A (and Q) reads done

            // Issue K(t+1) -> A, or prefetch NEXT item's Q + K (Qs/A both idle)
            if (tid == 0) {
                if ((kt + BN) < khi) {
                    uint32_t kb2 = (uint32_t)min(BM, N_TOK - (kt + BN)) * 512u;
                    fence_async();
                    mbar_expect(mbA, kb2);
                    bulk_g2s(a_u, K + (size_t)(kt + BN) * DHEAD, kb2, mbA);
                } else if (hasnext_item) {
                    uint32_t qb2 = (uint32_t)min(BM, N_TOK - r0n) * 512u;
                    uint32_t kb2 = (uint32_t)min(BM, N_TOK - klon) * 512u;
                    fence_async();
                    mbar_expect(mbA, qb2 + kb2);
                    bulk_g2s(qs_u, Q + (size_t)r0n * DHEAD, qb2, mbA);
                    bulk_g2s(a_u,  K + (size_t)klon * DHEAD, kb2, mbA);
                }
            }

            mbar_wait(mbB, phB); phB ^= 1;    // V(t) ready

            // ---- PV from B (linear, chunk = tx); P dup'd in registers ----
            const float* pp = Ps + (wy * 8) * 64;
            #pragma unroll 4
            for (int c2 = 0; c2 < 32; c2++) {
                const float* vrow = Bb + (2 * c2) * 128 + tx * 4;
                ulonglong2 vv0 = *(const ulonglong2*)(vrow);        // row 2c2
                ulonglong2 vv1 = *(const ulonglong2*)(vrow + 128);  // row 2c2+1
                #pragma unroll
                for (int i = 0; i < 8; i++) {
                    float2 pu = *(const float2*)(pp + i * 64 + c2 * 2);
                    unsigned long long d0 = dup2(pu.x);
                    unsigned long long d1 = dup2(pu.y);
                    fma2(o2[i][0], d0, vv0.x);
                    fma2(o2[i][1], d0, vv0.y);
                    fma2(o2[i][0], d1, vv1.x);
                    fma2(o2[i][1], d1, vv1.y);
                }
            }
            __syncthreads();                  // all B reads done before next V issue
        }
        prefetched = hasnext_item;            // next item's Q+K in flight

        // ---- epilogue: reduce l, store UNNORMALIZED partials ----
        #pragma unroll
        for (int i = 0; i < 8; i++) {
            float l = lsum[i];
            #pragma unroll
            for (int o = 16; o >= 1; o >>= 1)
                l += __shfl_xor_sync(0xffffffffu, l, o);
            int row = wy * 8 + i;
            if (row < nrows) {
                int gr = r0 + row;
                unsigned long long a = o2[i][0], bb = o2[i][1];
                float4 r4;
                r4.x = __uint_as_float((unsigned)a);
                r4.y = __uint_as_float((unsigned)(a >> 32));
                r4.z = __uint_as_float((unsigned)bb);
                r4.w = __uint_as_float((unsigned)(bb >> 32));
                *(float4*)&g_pO[part][gr][tx * 4] = r4;
                if (tx == 0) g_pl[part][gr] = l;
            }
        }
    }
}

// ---------------------------------------------------------------------------
// Combine: out[r] = sum_p pO[p][r] / sum_p pl[p][r]
// ---------------------------------------------------------------------------
__global__ void combine_kernel(const int* __restrict__ bseg,
                               float* __restrict__ out) {
    int idx = blockIdx.x * blockDim.x + threadIdx.x;   // 0 .. N_TOK*32-1
    int r  = idx >> 5;
    int c4 = idx & 31;
    int b  = bseg[r];
    int span = g_seg_start[b + 1] - g_seg_start[b];
    int np = (span + KSPLIT - 1) / KSPLIT;
    float4 a = *(const float4*)&g_pO[0][r][c4 * 4];
    float  l = g_pl[0][r];
    for (int p = 1; p < np; p++) {
        float4 t = *(const float4*)&g_pO[p][r][c4 * 4];
        a.x += t.x; a.y += t.y; a.z += t.z; a.w += t.w;
        l += g_pl[p][r];
    }
    float inv = 1.0f / l;   // EPS negligible (validated R2-R10)
    a.x *= inv; a.y *= inv; a.z *= inv; a.w *= inv;
    *(float4*)&out[(size_t)r * DHEAD + c4 * 4] = a;
}

// ---------------------------------------------------------------------------
extern "C" void kernel_launch(void* const* d_in, const int* in_sizes, int n_in,
                              void* d_out, int out_size) {
    const float* Q  = (const float*)d_in[0];
    const float* K  = (const float*)d_in[1];
    const float* V  = (const float*)d_in[2];
    const int* bseg = (const int*)d_in[n_in - 1];
    float* out      = (float*)d_out;

    const int smem_bytes = (8192 * 3 + 4096) * (int)sizeof(float);   // 112KB
    cudaFuncSetAttribute(attn_kernel, cudaFuncAttributeMaxDynamicSharedMemorySize,
                         smem_bytes);

    attn_kernel<<<NWORKERS, NTHREADS, smem_bytes>>>(Q, K, V, bseg);
    combine_kernel<<<N_TOK * 32 / 256, 256>>>(bseg, out);
}

// round 13
// speedup vs baseline: 1.1294x; 1.1294x over previous
#include <cuda_runtime.h>
#include <cstdint>

#define N_TOK 12288
#define DHEAD 128
#define NUMB  32
#define BM 64
#define BN 64
#define KSPLIT 128
#define MAXPARTS 6
#define NTHREADS 256
#define NWORKERS 296

__device__ int  g_seg_start[NUMB + 1];
__device__ int  g_ctr;
__device__ float g_pO[MAXPARTS][N_TOK][DHEAD];  // unnormalized partial O
__device__ float g_pl[MAXPARTS][N_TOK];          // partial row sums

// ---------------------------------------------------------------------------
// Prep (multi-block, one thread per token): boundary-detect segment starts.
// ---------------------------------------------------------------------------
__global__ void prep_kernel(const int* __restrict__ bseg) {
    int i = blockIdx.x * blockDim.x + threadIdx.x;
    if (i == 0) {
        g_ctr = 0;
        int c = bseg[0];
        for (int b = 0; b <= c; b++) g_seg_start[b] = 0;
        int last = bseg[N_TOK - 1];
        for (int b = last + 1; b <= NUMB; b++) g_seg_start[b] = N_TOK;
    } else if (i < N_TOK) {
        int a = bseg[i - 1], c = bseg[i];
        for (int b = a + 1; b <= c; b++) g_seg_start[b] = i;
    }
}

// ---------------------------------------------------------------------------
// PTX helpers
// ---------------------------------------------------------------------------
__device__ __forceinline__ void cp16(uint32_t dst, const void* src) {
    asm volatile("cp.async.cg.shared.global [%0], [%1], 16;" :: "r"(dst), "l"(src));
}
__device__ __forceinline__ void cp_commit() {
    asm volatile("cp.async.commit_group;" ::: "memory");
}
template <int NG> __device__ __forceinline__ void cp_wait() {
    asm volatile("cp.async.wait_group %0;" :: "n"(NG) : "memory");
}
__device__ __forceinline__ void fma2(unsigned long long& d,
                                     const unsigned long long a,
                                     const unsigned long long b) {
    asm volatile("fma.rn.f32x2 %0, %1, %2, %0;" : "+l"(d) : "l"(a), "l"(b));
}
__device__ __forceinline__ unsigned long long dup2(float x) {
    unsigned long long d;
    asm("mov.b64 %0, {%1, %1};" : "=l"(d) : "f"(x));
    return d;
}

// ---------------------------------------------------------------------------
// Main kernel (R9 champion core). 256 threads = 8 warps; warp wy owns rows
// wy*8..+7 of the item; lane tx owns score cols {2tx,2tx+1}, out cols 4tx..+3.
// Smem (112KB, 2 CTAs/SM): Q linear, A/B swizzled double-buffer, P (e0,e1).
// Pipeline: V(t)->B overlaps QK(t) on A; K(t+1)->A overlaps PV(t) on B.
// Dynamic atomic work queue; item mapping from per-CTA s_iofs prefix.
// ---------------------------------------------------------------------------
__global__ __launch_bounds__(NTHREADS, 2)
void attn_kernel(const float* __restrict__ Q, const float* __restrict__ K,
                 const float* __restrict__ V, const int* __restrict__ bseg) {
    extern __shared__ float smf[];
    float* Qs = smf;            // [64][128] 32KB linear
    float* Ab = smf + 8192;     // [64][128] 32KB swizzled (K tile)
    float* Bb = smf + 16384;    // [64][128] 32KB swizzled (V tile)
    float* Ps = smf + 24576;    // [64][64]  16KB (e0,e1) pairs
    __shared__ int s_seg[NUMB + 1];
    __shared__ int s_iofs[NUMB + 1];
    __shared__ int s_work;

    const int tid = threadIdx.x;
    const int tx  = tid & 31;
    const int wy  = tid >> 5;                 // 0..7
    const uint32_t sm_u = (uint32_t)__cvta_generic_to_shared(smf);
    const uint32_t qs_u = sm_u;
    const uint32_t a_u  = sm_u + 8192u * 4u;
    const uint32_t b_u  = sm_u + 16384u * 4u;
    const float isd = 0.0883883476483184f;    // 1/sqrt(128)
    const int ksw = tx & 7;                   // swizzle of rows 2tx,2tx+1

    // per-CTA: load seg table, build item-offset prefix
    if (tid <= NUMB) s_seg[tid] = g_seg_start[tid];
    __syncthreads();
    if (tid == 0) {
        int run = 0;
        for (int b2 = 0; b2 < NUMB; b2++) {
            s_iofs[b2] = run;
            int rows = s_seg[b2 + 1] - s_seg[b2];
            run += ((rows + BM - 1) / BM) * ((rows + KSPLIT - 1) / KSPLIT);
        }
        s_iofs[NUMB] = run;
    }
    __syncthreads();
    const int nitems = s_iofs[NUMB];

    while (true) {
        __syncthreads();                      // prev item's smem reads done
        if (tid == 0) s_work = atomicAdd(&g_ctr, 1);
        __syncthreads();
        const int w = s_work;
        if (w >= nitems) break;

        // map w -> (r0, nrows, klo, khi, part)
        int b2 = 0;
        while (w >= s_iofs[b2 + 1]) b2++;
        int rel = w - s_iofs[b2];
        int lo = s_seg[b2], hi = s_seg[b2 + 1];
        int nkp = (hi - lo + KSPLIT - 1) / KSPLIT;
        int rt  = rel / nkp;
        const int part  = rel - rt * nkp;
        const int r0    = lo + rt * BM;
        const int nrows = min(BM, hi - r0);
        const int klo   = lo + part * KSPLIT;
        const int khi   = min(klo + KSPLIT, hi);

        // Issue Q tile + first K tile (one async group)
        #pragma unroll
        for (int t = 0; t < 8; t++) {
            int idx = tid + t * NTHREADS;
            int r = idx >> 5, c4 = idx & 31;
            int gq = r0 + min(r, nrows - 1);
            cp16(qs_u + (r << 9) + (c4 << 4), Q + (size_t)gq * DHEAD + c4 * 4);
            int gk = klo + r; if (gk >= khi) gk = khi - 1;
            int off = (r << 9) + ((c4 ^ ((r >> 1) & 7)) << 4);
            cp16(a_u + off, K + (size_t)gk * DHEAD + c4 * 4);
        }
        cp_commit();

        unsigned long long o2[8][2];
        float lsum[8];
        #pragma unroll
        for (int i = 0; i < 8; i++) { o2[i][0] = 0ULL; o2[i][1] = 0ULL; lsum[i] = 0.f; }

        for (int kt = klo; kt < khi; kt += BN) {
            cp_wait<0>();                     // K(t) (and Q on first iter) done
            __syncthreads();                  // visible; B free (prev PV done)

            // Issue V(t) -> B (overlaps QK below)
            #pragma unroll
            for (int t = 0; t < 8; t++) {
                int idx = tid + t * NTHREADS;
                int r = idx >> 5, c4 = idx & 31;
                int gr = kt + r; if (gr >= khi) gr = khi - 1;
                int off = (r << 9) + ((c4 ^ ((r >> 1) & 7)) << 4);
                cp16(b_u + off, V + (size_t)gr * DHEAD + c4 * 4);
            }
            cp_commit();

            // ---- QK: 8 rows x 2 cols per lane, from A ----
            const float* kp0 = Ab + (2 * tx) * 128;
            const float* kp1 = kp0 + 128;
            const float* qp  = Qs + (wy * 8) * 128;
            unsigned long long s2[8][2];
            #pragma unroll
            for (int i = 0; i < 8; i++) { s2[i][0] = 0ULL; s2[i][1] = 0ULL; }

            #pragma unroll 4
            for (int c = 0; c < 32; c++) {
                int kph = (c ^ ksw) << 2;
                ulonglong2 ka = *(const ulonglong2*)(kp0 + kph);
                ulonglong2 kb = *(const ulonglong2*)(kp1 + kph);
                const float* qc = qp + (c << 2);
                #pragma unroll
                for (int i = 0; i < 8; i++) {
                    ulonglong2 qa = *(const ulonglong2*)(qc + i * 128);
                    fma2(s2[i][0], qa.x, ka.x);
                    fma2(s2[i][0], qa.y, ka.y);
                    fma2(s2[i][1], qa.x, kb.x);
                    fma2(s2[i][1], qa.y, kb.y);
                }
            }

            // ---- masked exp, P store (e0,e1) once ----
            const int col0 = kt + 2 * tx;
            #pragma unroll
            for (int i = 0; i < 8; i++) {
                unsigned long long v0 = s2[i][0], v1 = s2[i][1];
                float sv0 = (__uint_as_float((unsigned)v0) +
                             __uint_as_float((unsigned)(v0 >> 32))) * isd;
                float sv1 = (__uint_as_float((unsigned)v1) +
                             __uint_as_float((unsigned)(v1 >> 32))) * isd;
                float e0 = (col0     < khi) ? __expf(sv0) : 0.f;
                float e1 = (col0 + 1 < khi) ? __expf(sv1) : 0.f;
                lsum[i] += e0 + e1;
                float2 ev; ev.x = e0; ev.y = e1;
                *(float2*)(Ps + (wy * 8 + i) * 64 + tx * 2) = ev;
            }
            __syncthreads();                  // P visible; all A reads done

            // Issue K(t+1) -> A (overlaps PV below)
            const bool hasnext = (kt + BN) < khi;
            if (hasnext) {
                #pragma unroll
                for (int t = 0; t < 8; t++) {
                    int idx = tid + t * NTHREADS;
                    int r = idx >> 5, c4 = idx & 31;
                    int gr = kt + BN + r; if (gr >= khi) gr = khi - 1;
                    int off = (r << 9) + ((c4 ^ ((r >> 1) & 7)) << 4);
                    cp16(a_u + off, K + (size_t)gr * DHEAD + c4 * 4);
                }
                cp_commit();
                cp_wait<1>();                 // V(t) done; K(t+1) in flight
            } else {
                cp_wait<0>();                 // V(t) done
            }
            __syncthreads();                  // V visible

            // ---- PV from B; P pairs duplicated in registers ----
            const float* pp = Ps + (wy * 8) * 64;
            #pragma unroll 4
            for (int c2 = 0; c2 < 32; c2++) {
                int ph = (tx ^ (c2 & 7)) << 2;
                const float* vrow = Bb + (2 * c2) * 128 + ph;
                ulonglong2 vv0 = *(const ulonglong2*)(vrow);        // row 2c2
                ulonglong2 vv1 = *(const ulonglong2*)(vrow + 128);  // row 2c2+1
                #pragma unroll
                for (int i = 0; i < 8; i++) {
                    float2 pu = *(const float2*)(pp + i * 64 + c2 * 2);
                    unsigned long long d0 = dup2(pu.x);
                    unsigned long long d1 = dup2(pu.y);
                    fma2(o2[i][0], d0, vv0.x);
                    fma2(o2[i][1], d0, vv0.y);
                    fma2(o2[i][0], d1, vv1.x);
                    fma2(o2[i][1], d1, vv1.y);
                }
            }
        }

        // ---- epilogue: reduce l, store UNNORMALIZED partials ----
        #pragma unroll
        for (int i = 0; i < 8; i++) {
            float l = lsum[i];
            #pragma unroll
            for (int o = 16; o >= 1; o >>= 1)
                l += __shfl_xor_sync(0xffffffffu, l, o);
            int row = wy * 8 + i;
            if (row < nrows) {
                int gr = r0 + row;
                unsigned long long a = o2[i][0], bb = o2[i][1];
                float4 r4;
                r4.x = __uint_as_float((unsigned)a);
                r4.y = __uint_as_float((unsigned)(a >> 32));
                r4.z = __uint_as_float((unsigned)bb);
                r4.w = __uint_as_float((unsigned)(bb >> 32));
                *(float4*)&g_pO[part][gr][tx * 4] = r4;
                if (tx == 0) g_pl[part][gr] = l;
            }
        }
    }
}

// ---------------------------------------------------------------------------
// Combine: out[r] = sum_p pO[p][r] / sum_p pl[p][r]
// ---------------------------------------------------------------------------
__global__ void combine_kernel(const int* __restrict__ bseg,
                               float* __restrict__ out) {
    int idx = blockIdx.x * blockDim.x + threadIdx.x;   // 0 .. N_TOK*32-1
    int r  = idx >> 5;
    int c4 = idx & 31;
    int b  = bseg[r];
    int span = g_seg_start[b + 1] - g_seg_start[b];
    int np = (span + KSPLIT - 1) / KSPLIT;
    float4 a = *(const float4*)&g_pO[0][r][c4 * 4];
    float  l = g_pl[0][r];
    for (int p = 1; p < np; p++) {
        float4 t = *(const float4*)&g_pO[p][r][c4 * 4];
        a.x += t.x; a.y += t.y; a.z += t.z; a.w += t.w;
        l += g_pl[p][r];
    }
    float inv = 1.0f / l;   // EPS negligible (validated R2-R11)
    a.x *= inv; a.y *= inv; a.z *= inv; a.w *= inv;
    *(float4*)&out[(size_t)r * DHEAD + c4 * 4] = a;
}

// ---------------------------------------------------------------------------
extern "C" void kernel_launch(void* const* d_in, const int* in_sizes, int n_in,
                              void* d_out, int out_size) {
    const float* Q  = (const float*)d_in[0];
    const float* K  = (const float*)d_in[1];
    const float* V  = (const float*)d_in[2];
    const int* bseg = (const int*)d_in[n_in - 1];
    float* out      = (float*)d_out;

    const int smem_bytes = (8192 * 3 + 4096) * (int)sizeof(float);   // 112KB
    cudaFuncSetAttribute(attn_kernel, cudaFuncAttributeMaxDynamicSharedMemorySize,
                         smem_bytes);

    prep_kernel<<<N_TOK / 256, 256>>>(bseg);
    attn_kernel<<<NWORKERS, NTHREADS, smem_bytes>>>(Q, K, V, bseg);
    combine_kernel<<<N_TOK * 32 / 256, 256>>>(bseg, out);
}